// round 3
// baseline (speedup 1.0000x reference)
#include <cuda_runtime.h>
#include <cstdint>

// Problem constants (fixed by the reference: B=8, C=512, T=2048)
#define NB 8
#define NC 512
#define NT 2048

// ---------------- scratch (device globals; no allocation allowed) ----------
__device__ float g_theta  [(size_t)NB * NC * NT];   // 32 MB
__device__ float g_phi    [(size_t)NB * NC * NT];   // 32 MB
__device__ float g_gf     [(size_t)NB * NC * NT];   // 32 MB
__device__ float g_scores [(size_t)NB * NT * NT];   // 128 MB (scores, then attn in-place)
__device__ float g_feature[(size_t)NB * NC * NT];   // 32 MB

// ---------------- helpers ---------------------------------------------------
__device__ __forceinline__ float f2tf(float f) {
    uint32_t u;
    asm("cvt.rna.tf32.f32 %0, %1;" : "=r"(u) : "f"(f));
    return __uint_as_float(u);
}

__device__ __forceinline__ void mma8(float* d, const uint32_t* a, const uint32_t* b) {
    asm volatile(
        "mma.sync.aligned.m16n8k8.row.col.f32.tf32.tf32.f32 "
        "{%0,%1,%2,%3}, {%4,%5,%6,%7}, {%8,%9}, {%0,%1,%2,%3};"
        : "+f"(d[0]), "+f"(d[1]), "+f"(d[2]), "+f"(d[3])
        : "r"(a[0]), "r"(a[1]), "r"(a[2]), "r"(a[3]),
          "r"(b[0]), "r"(b[1]));
}

// ---------------- generic TF32 GEMM -----------------------------------------
// C[M,N] = op_A(A) * op_B(B)
//  TA=false: A global is [M,K] row-major (ld = lda)
//  TA=true : A global is [K,M] row-major (ld = lda)   (i.e. A^T view)
//  TB=false: B global is [K,N] row-major (ld = ldb)
//  TB=true : B global is [N,K] row-major (ld = ldb)   (i.e. B^T view)
// EPI: 0 = plain store, 1 = relu(acc + bias[m]), 2 = relu(acc + bias[m]) + res[m,n]
// Grid: (N/128, M/128, batch). K, lda, ldb, ldo all divisible by our tiles here.
template<bool TA, bool TB, int EPI>
__global__ void __launch_bounds__(256, 1)
gemm_tf32(const float* __restrict__ A, const float* __restrict__ B,
          float* __restrict__ out,
          int lda, int ldb, int ldo, int K,
          long long sA, long long sB, long long sO,
          const float* __restrict__ bias,
          const float* __restrict__ res, long long sR)
{
    constexpr int BM = 128, BN = 128, BK = 32, PAD = 8;
    __shared__ float As[BK][BM + PAD];   // [k][m]
    __shared__ float Bs[BK][BN + PAD];   // [k][n]

    const int tid = threadIdx.x;
    const int bn = blockIdx.x, bm = blockIdx.y, bz = blockIdx.z;

    A   += (long long)bz * sA;
    B   += (long long)bz * sB;
    out += (long long)bz * sO;
    if constexpr (EPI == 2) res += (long long)bz * sR;

    if constexpr (!TA) A += (long long)bm * BM * lda;
    else               A += bm * BM;
    if constexpr (!TB) B += bn * BN;
    else               B += (long long)bn * BN * ldb;

    const int warp = tid >> 5, lane = tid & 31;
    const int wm = warp >> 1, wn = warp & 1;         // 4 x 2 warp grid
    const int r = lane & 3, q = lane >> 2;

    float acc[2][8][4];
    #pragma unroll
    for (int i = 0; i < 2; i++)
        #pragma unroll
        for (int j = 0; j < 8; j++)
            #pragma unroll
            for (int c = 0; c < 4; c++) acc[i][j][c] = 0.f;

    float4 pa[4], pb[4];

    auto ldgA = [&](int kt) {
        const int k0 = kt * BK;
        if constexpr (!TA) {
            // [M,K]: thread owns row m=tid&127, 16 consecutive k
            const float* p = A + (long long)(tid & 127) * lda + k0 + ((tid >> 7) << 4);
            #pragma unroll
            for (int i = 0; i < 4; i++) pa[i] = *(const float4*)(p + i * 4);
        } else {
            // [K,M]: thread owns k-row tid>>5, 4 consecutive m
            const float* p = A + (long long)(k0 + (tid >> 5)) * lda + ((tid & 31) << 2);
            #pragma unroll
            for (int i = 0; i < 4; i++) pa[i] = *(const float4*)(p + (long long)i * 8 * lda);
        }
    };
    auto ldgB = [&](int kt) {
        const int k0 = kt * BK;
        if constexpr (!TB) {
            const float* p = B + (long long)(k0 + (tid >> 5)) * ldb + ((tid & 31) << 2);
            #pragma unroll
            for (int i = 0; i < 4; i++) pb[i] = *(const float4*)(p + (long long)i * 8 * ldb);
        } else {
            const float* p = B + (long long)(tid & 127) * ldb + k0 + ((tid >> 7) << 4);
            #pragma unroll
            for (int i = 0; i < 4; i++) pb[i] = *(const float4*)(p + i * 4);
        }
    };
    auto stsA = [&]() {
        if constexpr (!TA) {
            const int m = tid & 127, kb = (tid >> 7) << 4;
            #pragma unroll
            for (int i = 0; i < 4; i++) {
                const int k = kb + i * 4;
                As[k + 0][m] = f2tf(pa[i].x);
                As[k + 1][m] = f2tf(pa[i].y);
                As[k + 2][m] = f2tf(pa[i].z);
                As[k + 3][m] = f2tf(pa[i].w);
            }
        } else {
            const int k = tid >> 5, m4 = (tid & 31) << 2;
            #pragma unroll
            for (int i = 0; i < 4; i++) {
                float4 v;
                v.x = f2tf(pa[i].x); v.y = f2tf(pa[i].y);
                v.z = f2tf(pa[i].z); v.w = f2tf(pa[i].w);
                *(float4*)&As[k + i * 8][m4] = v;
            }
        }
    };
    auto stsB = [&]() {
        if constexpr (!TB) {
            const int k = tid >> 5, n4 = (tid & 31) << 2;
            #pragma unroll
            for (int i = 0; i < 4; i++) {
                float4 v;
                v.x = f2tf(pb[i].x); v.y = f2tf(pb[i].y);
                v.z = f2tf(pb[i].z); v.w = f2tf(pb[i].w);
                *(float4*)&Bs[k + i * 8][n4] = v;
            }
        } else {
            const int n = tid & 127, kb = (tid >> 7) << 4;
            #pragma unroll
            for (int i = 0; i < 4; i++) {
                const int k = kb + i * 4;
                Bs[k + 0][n] = f2tf(pb[i].x);
                Bs[k + 1][n] = f2tf(pb[i].y);
                Bs[k + 2][n] = f2tf(pb[i].z);
                Bs[k + 3][n] = f2tf(pb[i].w);
            }
        }
    };

    const int nk = K / BK;
    ldgA(0); ldgB(0);

    for (int kt = 0; kt < nk; ++kt) {
        stsA(); stsB();
        __syncthreads();
        if (kt + 1 < nk) { ldgA(kt + 1); ldgB(kt + 1); }

        #pragma unroll
        for (int ks = 0; ks < 4; ++ks) {
            const int kk = ks * 8;
            uint32_t af[2][4], bf[8][2];
            #pragma unroll
            for (int mt = 0; mt < 2; ++mt) {
                const int mrow = wm * 32 + mt * 16 + q;
                af[mt][0] = __float_as_uint(As[kk + r    ][mrow    ]);
                af[mt][1] = __float_as_uint(As[kk + r    ][mrow + 8]);
                af[mt][2] = __float_as_uint(As[kk + r + 4][mrow    ]);
                af[mt][3] = __float_as_uint(As[kk + r + 4][mrow + 8]);
            }
            #pragma unroll
            for (int nt = 0; nt < 8; ++nt) {
                const int nc = wn * 64 + nt * 8 + q;
                bf[nt][0] = __float_as_uint(Bs[kk + r    ][nc]);
                bf[nt][1] = __float_as_uint(Bs[kk + r + 4][nc]);
            }
            #pragma unroll
            for (int mt = 0; mt < 2; ++mt)
                #pragma unroll
                for (int nt = 0; nt < 8; ++nt)
                    mma8(acc[mt][nt], af[mt], bf[nt]);
        }
        __syncthreads();
    }

    // epilogue: c0,c1 -> (row q, cols 2r,2r+1); c2,c3 -> row q+8
    const int gm0 = bm * BM + wm * 32 + q;
    const int gn0 = bn * BN + wn * 64 + 2 * r;
    #pragma unroll
    for (int mt = 0; mt < 2; ++mt) {
        #pragma unroll
        for (int h = 0; h < 2; ++h) {
            const int row = gm0 + mt * 16 + h * 8;
            float bv = 0.f;
            if constexpr (EPI >= 1) bv = bias[row];
            float* op = out + (long long)row * ldo;
            const float* rp = nullptr;
            if constexpr (EPI == 2) rp = res + (long long)row * ldo;
            #pragma unroll
            for (int nt = 0; nt < 8; ++nt) {
                const int gn = gn0 + nt * 8;
                float c0 = acc[mt][nt][2 * h + 0];
                float c1 = acc[mt][nt][2 * h + 1];
                if constexpr (EPI >= 1) {
                    c0 = fmaxf(c0 + bv, 0.f);
                    c1 = fmaxf(c1 + bv, 0.f);
                }
                if constexpr (EPI == 2) { c0 += rp[gn]; c1 += rp[gn + 1]; }
                float2 v; v.x = c0; v.y = c1;
                *(float2*)(op + gn) = v;
            }
        }
    }
}

// ---------------- row softmax over 2048 elements, in place ------------------
// grid (NT, NB), block 256; each CTA owns one row.
__global__ void __launch_bounds__(256, 4)
softmax2048(float* __restrict__ S)
{
    float* row = S + ((size_t)blockIdx.y * NT + blockIdx.x) * NT;
    const int tid = threadIdx.x;
    const int warp = tid >> 5, lane = tid & 31;

    float4 v0 = ((const float4*)row)[tid];
    float4 v1 = ((const float4*)row)[tid + 256];

    float mx = fmaxf(fmaxf(fmaxf(v0.x, v0.y), fmaxf(v0.z, v0.w)),
                     fmaxf(fmaxf(v1.x, v1.y), fmaxf(v1.z, v1.w)));
    #pragma unroll
    for (int o = 16; o; o >>= 1) mx = fmaxf(mx, __shfl_xor_sync(0xffffffffu, mx, o));

    __shared__ float sm[8], ss[8];
    if (!lane) sm[warp] = mx;
    __syncthreads();
    mx = sm[0];
    #pragma unroll
    for (int i = 1; i < 8; i++) mx = fmaxf(mx, sm[i]);

    v0.x = __expf(v0.x - mx); v0.y = __expf(v0.y - mx);
    v0.z = __expf(v0.z - mx); v0.w = __expf(v0.w - mx);
    v1.x = __expf(v1.x - mx); v1.y = __expf(v1.y - mx);
    v1.z = __expf(v1.z - mx); v1.w = __expf(v1.w - mx);

    float s = v0.x + v0.y + v0.z + v0.w + v1.x + v1.y + v1.z + v1.w;
    #pragma unroll
    for (int o = 16; o; o >>= 1) s += __shfl_xor_sync(0xffffffffu, s, o);
    if (!lane) ss[warp] = s;
    __syncthreads();
    s = ss[0];
    #pragma unroll
    for (int i = 1; i < 8; i++) s += ss[i];

    const float inv = 1.0f / s;
    v0.x *= inv; v0.y *= inv; v0.z *= inv; v0.w *= inv;
    v1.x *= inv; v1.y *= inv; v1.z *= inv; v1.w *= inv;
    ((float4*)row)[tid]       = v0;
    ((float4*)row)[tid + 256] = v1;
}

// ---------------- launch ----------------------------------------------------
extern "C" void kernel_launch(void* const* d_in, const int* in_sizes, int n_in,
                              void* d_out, int out_size)
{
    const float* x       = (const float*)d_in[0];
    const float* w_theta = (const float*)d_in[1];
    const float* b_theta = (const float*)d_in[2];
    const float* w_phi   = (const float*)d_in[3];
    const float* b_phi   = (const float*)d_in[4];
    const float* w_g     = (const float*)d_in[5];
    const float* b_g     = (const float*)d_in[6];
    const float* w_w     = (const float*)d_in[7];
    const float* b_w     = (const float*)d_in[8];

    void *pt, *pp, *pg, *ps, *pf;
    cudaGetSymbolAddress(&pt, g_theta);
    cudaGetSymbolAddress(&pp, g_phi);
    cudaGetSymbolAddress(&pg, g_gf);
    cudaGetSymbolAddress(&ps, g_scores);
    cudaGetSymbolAddress(&pf, g_feature);
    float* theta = (float*)pt;
    float* phi   = (float*)pp;
    float* gf    = (float*)pg;
    float* sc    = (float*)ps;
    float* feat  = (float*)pf;

    const long long sCT = (long long)NC * NT;   // per-batch [C,T] stride
    const long long sTT = (long long)NT * NT;   // per-batch [T,T] stride

    dim3 blk(256);
    dim3 gconv(NT / 128, NC / 128, NB);   // (16, 4, 8)
    dim3 gsc  (NT / 128, NT / 128, NB);   // (16, 16, 8)

    // theta/phi/g = relu(W @ x + b) : A=[C,C] row-major, B=x_b [C,T]
    gemm_tf32<false, false, 1><<<gconv, blk>>>(w_theta, x, theta,
        NC, NT, NT, NC, 0, sCT, sCT, b_theta, nullptr, 0);
    gemm_tf32<false, false, 1><<<gconv, blk>>>(w_phi, x, phi,
        NC, NT, NT, NC, 0, sCT, sCT, b_phi, nullptr, 0);
    gemm_tf32<false, false, 1><<<gconv, blk>>>(w_g, x, gf,
        NC, NT, NT, NC, 0, sCT, sCT, b_g, nullptr, 0);

    // scores[i,j] = sum_c theta[c,i] * phi[c,j]  -> A^T (theta [C,T]), B (phi [C,T])
    gemm_tf32<true, false, 0><<<gsc, blk>>>(theta, phi, sc,
        NT, NT, NT, NC, sCT, sCT, sTT, nullptr, nullptr, 0);

    // softmax over j (rows of [T,T]), in place
    softmax2048<<<dim3(NT, NB), blk>>>(sc);

    // feature[c,i] = sum_j g[c,j] * attn[i,j] -> A (g [C,T]), B^T (attn [T,T])
    gemm_tf32<false, true, 0><<<gconv, blk>>>(gf, sc, feat,
        NT, NT, NT, NT, sCT, sTT, sCT, nullptr, nullptr, 0);

    // out = relu(W_w @ feature + b_w) + x
    gemm_tf32<false, false, 2><<<gconv, blk>>>(w_w, feat, (float*)d_out,
        NC, NT, NT, NC, 0, sCT, sCT, b_w, x, sCT);
}

// round 4
// speedup vs baseline: 1.5087x; 1.5087x over previous
#include <cuda_runtime.h>
#include <cstdint>

// Problem constants (fixed by the reference: B=8, C=512, T=2048)
#define NB 8
#define NC 512
#define NT 2048

// ---------------- scratch (device globals; no allocation allowed) ----------
__device__ float g_theta  [(size_t)NB * NC * NT];   // 32 MB (tf32-rounded)
__device__ float g_phi    [(size_t)NB * NC * NT];   // 32 MB (tf32-rounded)
__device__ float g_gf     [(size_t)NB * NC * NT];   // 32 MB (tf32-rounded)
__device__ float g_scores [(size_t)NB * NT * NT];   // 128 MB (scores, then attn)
__device__ float g_feature[(size_t)NB * NC * NT];   // 32 MB (tf32-rounded)

// ---------------- helpers ---------------------------------------------------
__device__ __forceinline__ float f2tf(float f) {
    uint32_t u;
    asm("cvt.rna.tf32.f32 %0, %1;" : "=r"(u) : "f"(f));
    return __uint_as_float(u);
}

__device__ __forceinline__ void mma8(float* d, const uint32_t* a, const uint32_t* b) {
    asm volatile(
        "mma.sync.aligned.m16n8k8.row.col.f32.tf32.tf32.f32 "
        "{%0,%1,%2,%3}, {%4,%5,%6,%7}, {%8,%9}, {%0,%1,%2,%3};"
        : "+f"(d[0]), "+f"(d[1]), "+f"(d[2]), "+f"(d[3])
        : "r"(a[0]), "r"(a[1]), "r"(a[2]), "r"(a[3]),
          "r"(b[0]), "r"(b[1]));
}

__device__ __forceinline__ void cpa16(void* dst, const void* src) {
    uint32_t d = (uint32_t)__cvta_generic_to_shared(dst);
    asm volatile("cp.async.cg.shared.global [%0], [%1], 16;" :: "r"(d), "l"(src));
}
__device__ __forceinline__ void cpa_commit() {
    asm volatile("cp.async.commit_group;" ::: "memory");
}
template<int N>
__device__ __forceinline__ void cpa_wait() {
    asm volatile("cp.async.wait_group %0;" :: "n"(N) : "memory");
}

// ---------------- generic TF32 GEMM, cp.async 3-stage pipeline ---------------
// C[M,N] = op_A(A) * op_B(B)
//  TA=false: A global is [M,K] row-major   TA=true: A global is [K,M] (A^T view)
//  TB=false: B global is [K,N] row-major   TB=true: B global is [N,K] (B^T view)
//  CVA/CVB: round fragment to tf32 at load (needed only for raw fp32 inputs)
//  EPI: 0 plain, 1 relu(acc+bias[m]), 2 relu(acc+bias[m])+res
//  RND: round stored output to tf32 (so consumers can skip CVT)
// CTA tile 256x128x32, 8 warps of 64x64. All dims divide tiles here.
template<bool TA, bool TB, bool CVA, bool CVB, int EPI, bool RND>
__global__ void __launch_bounds__(256, 1)
gemm_tf32(const float* __restrict__ A, const float* __restrict__ B,
          float* __restrict__ out,
          int lda, int ldb, int ldo, int K,
          long long sA, long long sB, long long sO,
          const float* __restrict__ bias,
          const float* __restrict__ res, long long sR)
{
    constexpr int BM = 256, BN = 128, BK = 32;
    constexpr int A_LD = TA ? (BM + 8) : (BK + 4);
    constexpr int B_LD = TB ? (BK + 4) : (BN + 8);
    constexpr int A_SZ = TA ? BK * A_LD : BM * A_LD;
    constexpr int B_SZ = TB ? BN * B_LD : BK * B_LD;
    constexpr int STAGES = 3;

    extern __shared__ float smem[];
    float* Abase = smem;
    float* Bbase = smem + STAGES * A_SZ;

    const int tid = threadIdx.x;
    const int bn = blockIdx.x, bm = blockIdx.y, bz = blockIdx.z;

    A   += (long long)bz * sA;
    B   += (long long)bz * sB;
    out += (long long)bz * sO;
    if constexpr (EPI == 2) res += (long long)bz * sR;

    if constexpr (!TA) A += (long long)bm * BM * lda;
    else               A += bm * BM;
    if constexpr (!TB) B += bn * BN;
    else               B += (long long)bn * BN * ldb;

    const int warp = tid >> 5, lane = tid & 31;
    const int wm = warp >> 1, wn = warp & 1;       // 4 x 2 warps, 64x64 each
    const int r = lane & 3, q = lane >> 2;

    float acc[4][8][4];
    #pragma unroll
    for (int i = 0; i < 4; i++)
        #pragma unroll
        for (int j = 0; j < 8; j++)
            #pragma unroll
            for (int c = 0; c < 4; c++) acc[i][j][c] = 0.f;

    auto issueA = [&](int kt, float* Asm) {
        const int k0 = kt * BK;
        if constexpr (!TA) {
            // [M,K]: thread owns row tid, 32 consecutive k (8 x 16B)
            const float* src = A + (long long)tid * lda + k0;
            float* dst = Asm + tid * A_LD;
            #pragma unroll
            for (int i = 0; i < 8; i++) cpa16(dst + i * 4, src + i * 4);
        } else {
            // [K,M]: k-row tid>>3, 8 threads/row, 8 x 16B each along m
            const int k = tid >> 3, m0 = (tid & 7) * 4;
            const float* src = A + (long long)(k0 + k) * lda + m0;
            float* dst = Asm + k * A_LD + m0;
            #pragma unroll
            for (int i = 0; i < 8; i++) cpa16(dst + i * 32, src + i * 32);
        }
    };
    auto issueB = [&](int kt, float* Bsm) {
        const int k0 = kt * BK;
        if constexpr (!TB) {
            // [K,N]: k-row tid>>3, 8 threads/row, 4 x 16B each along n
            const int k = tid >> 3, n0 = (tid & 7) * 4;
            const float* src = B + (long long)(k0 + k) * ldb + n0;
            float* dst = Bsm + k * B_LD + n0;
            #pragma unroll
            for (int i = 0; i < 4; i++) cpa16(dst + i * 32, src + i * 32);
        } else {
            // [N,K]: n-row tid>>1, 2 threads/row, 4 x 16B each along k
            const int n = tid >> 1, kk0 = (tid & 1) * 4;
            const float* src = B + (long long)n * ldb + k0 + kk0;
            float* dst = Bsm + n * B_LD + kk0;
            #pragma unroll
            for (int i = 0; i < 4; i++) cpa16(dst + i * 8, src + i * 8);
        }
    };

    auto rdA = [&](const float* p) -> uint32_t {
        float v = *p;
        if constexpr (CVA) v = f2tf(v);
        return __float_as_uint(v);
    };
    auto rdB = [&](const float* p) -> uint32_t {
        float v = *p;
        if constexpr (CVB) v = f2tf(v);
        return __float_as_uint(v);
    };

    const int nk = K / BK;

    issueA(0, Abase);          issueB(0, Bbase);          cpa_commit();
    issueA(1, Abase + A_SZ);   issueB(1, Bbase + B_SZ);   cpa_commit();

    for (int kt = 0; kt < nk; ++kt) {
        cpa_wait<1>();            // stage kt resident
        __syncthreads();          // + all warps done with buffer (kt)%3's last use

        const int nx = kt + 2;
        if (nx < nk) {
            const int sb = nx % STAGES;
            issueA(nx, Abase + sb * A_SZ);
            issueB(nx, Bbase + sb * B_SZ);
        }
        cpa_commit();             // keep group count uniform (empty groups ok)

        const float* Asm = Abase + (kt % STAGES) * A_SZ;
        const float* Bsm = Bbase + (kt % STAGES) * B_SZ;

        #pragma unroll
        for (int ks = 0; ks < 4; ++ks) {
            const int kk = ks * 8;
            uint32_t af[4][4], bf[8][2];
            #pragma unroll
            for (int mt = 0; mt < 4; ++mt) {
                const int m0 = wm * 64 + mt * 16 + q;
                if constexpr (!TA) {
                    const float* p = Asm + (size_t)m0 * A_LD + kk + r;
                    af[mt][0] = rdA(p);
                    af[mt][1] = rdA(p + 8 * A_LD);
                    af[mt][2] = rdA(p + 4);
                    af[mt][3] = rdA(p + 8 * A_LD + 4);
                } else {
                    const float* p = Asm + (size_t)(kk + r) * A_LD + m0;
                    af[mt][0] = rdA(p);
                    af[mt][1] = rdA(p + 8);
                    af[mt][2] = rdA(p + 4 * A_LD);
                    af[mt][3] = rdA(p + 4 * A_LD + 8);
                }
            }
            #pragma unroll
            for (int nt = 0; nt < 8; ++nt) {
                const int n0 = wn * 64 + nt * 8 + q;
                if constexpr (!TB) {
                    const float* p = Bsm + (size_t)(kk + r) * B_LD + n0;
                    bf[nt][0] = rdB(p);
                    bf[nt][1] = rdB(p + 4 * B_LD);
                } else {
                    const float* p = Bsm + (size_t)n0 * B_LD + kk + r;
                    bf[nt][0] = rdB(p);
                    bf[nt][1] = rdB(p + 4);
                }
            }
            #pragma unroll
            for (int mt = 0; mt < 4; ++mt)
                #pragma unroll
                for (int nt = 0; nt < 8; ++nt)
                    mma8(acc[mt][nt], af[mt], bf[nt]);
        }
    }

    // epilogue: c0,c1 -> (row q, cols 2r,2r+1); c2,c3 -> row q+8
    #pragma unroll
    for (int mt = 0; mt < 4; ++mt) {
        #pragma unroll
        for (int h = 0; h < 2; ++h) {
            const int row = bm * BM + wm * 64 + mt * 16 + h * 8 + q;
            float bv = 0.f;
            if constexpr (EPI >= 1) bv = bias[row];
            float* op = out + (long long)row * ldo;
            const float* rp = nullptr;
            if constexpr (EPI == 2) rp = res + (long long)row * ldo;
            #pragma unroll
            for (int nt = 0; nt < 8; ++nt) {
                const int gn = bn * BN + wn * 64 + nt * 8 + 2 * r;
                float c0 = acc[mt][nt][2 * h + 0];
                float c1 = acc[mt][nt][2 * h + 1];
                if constexpr (EPI >= 1) {
                    c0 = fmaxf(c0 + bv, 0.f);
                    c1 = fmaxf(c1 + bv, 0.f);
                }
                if constexpr (EPI == 2) { c0 += rp[gn]; c1 += rp[gn + 1]; }
                if constexpr (RND) { c0 = f2tf(c0); c1 = f2tf(c1); }
                float2 v; v.x = c0; v.y = c1;
                *(float2*)(op + gn) = v;
            }
        }
    }
}

// ---------------- row softmax over 2048 elements, in place ------------------
// Stores tf32-rounded probabilities (consumer GEMM skips cvt).
__global__ void __launch_bounds__(256, 4)
softmax2048(float* __restrict__ S)
{
    float* row = S + ((size_t)blockIdx.y * NT + blockIdx.x) * NT;
    const int tid = threadIdx.x;
    const int warp = tid >> 5, lane = tid & 31;

    float4 v0 = ((const float4*)row)[tid];
    float4 v1 = ((const float4*)row)[tid + 256];

    float mx = fmaxf(fmaxf(fmaxf(v0.x, v0.y), fmaxf(v0.z, v0.w)),
                     fmaxf(fmaxf(v1.x, v1.y), fmaxf(v1.z, v1.w)));
    #pragma unroll
    for (int o = 16; o; o >>= 1) mx = fmaxf(mx, __shfl_xor_sync(0xffffffffu, mx, o));

    __shared__ float sm[8], ss[8];
    if (!lane) sm[warp] = mx;
    __syncthreads();
    mx = sm[0];
    #pragma unroll
    for (int i = 1; i < 8; i++) mx = fmaxf(mx, sm[i]);

    v0.x = __expf(v0.x - mx); v0.y = __expf(v0.y - mx);
    v0.z = __expf(v0.z - mx); v0.w = __expf(v0.w - mx);
    v1.x = __expf(v1.x - mx); v1.y = __expf(v1.y - mx);
    v1.z = __expf(v1.z - mx); v1.w = __expf(v1.w - mx);

    float s = v0.x + v0.y + v0.z + v0.w + v1.x + v1.y + v1.z + v1.w;
    #pragma unroll
    for (int o = 16; o; o >>= 1) s += __shfl_xor_sync(0xffffffffu, s, o);
    if (!lane) ss[warp] = s;
    __syncthreads();
    s = ss[0];
    #pragma unroll
    for (int i = 1; i < 8; i++) s += ss[i];

    const float inv = 1.0f / s;
    v0.x = f2tf(v0.x * inv); v0.y = f2tf(v0.y * inv);
    v0.z = f2tf(v0.z * inv); v0.w = f2tf(v0.w * inv);
    v1.x = f2tf(v1.x * inv); v1.y = f2tf(v1.y * inv);
    v1.z = f2tf(v1.z * inv); v1.w = f2tf(v1.w * inv);
    ((float4*)row)[tid]       = v0;
    ((float4*)row)[tid + 256] = v1;
}

// ---------------- launch ----------------------------------------------------
static inline int smem_for(bool ta, bool tb) {
    int a = ta ? 32 * (256 + 8) : 256 * (32 + 4);
    int b = tb ? 128 * (32 + 4) : 32 * (128 + 8);
    return 3 * (a + b) * (int)sizeof(float);
}

extern "C" void kernel_launch(void* const* d_in, const int* in_sizes, int n_in,
                              void* d_out, int out_size)
{
    const float* x       = (const float*)d_in[0];
    const float* w_theta = (const float*)d_in[1];
    const float* b_theta = (const float*)d_in[2];
    const float* w_phi   = (const float*)d_in[3];
    const float* b_phi   = (const float*)d_in[4];
    const float* w_g     = (const float*)d_in[5];
    const float* b_g     = (const float*)d_in[6];
    const float* w_w     = (const float*)d_in[7];
    const float* b_w     = (const float*)d_in[8];

    void *pt, *pp, *pg, *ps, *pf;
    cudaGetSymbolAddress(&pt, g_theta);
    cudaGetSymbolAddress(&pp, g_phi);
    cudaGetSymbolAddress(&pg, g_gf);
    cudaGetSymbolAddress(&ps, g_scores);
    cudaGetSymbolAddress(&pf, g_feature);
    float* theta = (float*)pt;
    float* phi   = (float*)pp;
    float* gf    = (float*)pg;
    float* sc    = (float*)ps;
    float* feat  = (float*)pf;

    const long long sCT = (long long)NC * NT;   // per-batch [C,T] stride
    const long long sTT = (long long)NT * NT;   // per-batch [T,T] stride

    // kernel instantiations
    auto kconv  = gemm_tf32<false, false, true,  true,  1, true >;  // relu(Wx+b), tf32-out
    auto kscore = gemm_tf32<true,  false, false, false, 0, false>;  // theta^T phi
    auto kfeat  = gemm_tf32<false, true,  false, false, 0, true >;  // g @ attn^T, tf32-out
    auto kfinal = gemm_tf32<false, false, true,  false, 2, false>;  // relu(Wf+b)+x

    const int smNN = smem_for(false, false);
    const int smTN = smem_for(true,  false);
    const int smNT = smem_for(false, true);
    cudaFuncSetAttribute(kconv,  cudaFuncAttributeMaxDynamicSharedMemorySize, smNN);
    cudaFuncSetAttribute(kscore, cudaFuncAttributeMaxDynamicSharedMemorySize, smTN);
    cudaFuncSetAttribute(kfeat,  cudaFuncAttributeMaxDynamicSharedMemorySize, smNT);
    cudaFuncSetAttribute(kfinal, cudaFuncAttributeMaxDynamicSharedMemorySize, smNN);

    dim3 blk(256);
    dim3 gconv(NT / 128, NC / 256, NB);   // (16, 2, 8)
    dim3 gsc  (NT / 128, NT / 256, NB);   // (16, 8, 8)

    // theta/phi/g = relu(W @ x + b), stored tf32-rounded
    kconv<<<gconv, blk, smNN>>>(w_theta, x, theta, NC, NT, NT, NC, 0, sCT, sCT, b_theta, nullptr, 0);
    kconv<<<gconv, blk, smNN>>>(w_phi,   x, phi,   NC, NT, NT, NC, 0, sCT, sCT, b_phi,   nullptr, 0);
    kconv<<<gconv, blk, smNN>>>(w_g,     x, gf,    NC, NT, NT, NC, 0, sCT, sCT, b_g,     nullptr, 0);

    // scores[i,j] = sum_c theta[c,i] * phi[c,j]
    kscore<<<gsc, blk, smTN>>>(theta, phi, sc, NT, NT, NT, NC, sCT, sCT, sTT, nullptr, nullptr, 0);

    // softmax over j, in place, tf32-rounded output
    softmax2048<<<dim3(NT, NB), blk>>>(sc);

    // feature[c,i] = sum_j g[c,j] * attn[i,j]
    kfeat<<<gconv, blk, smNT>>>(gf, sc, feat, NT, NT, NT, NT, sCT, sTT, sCT, nullptr, nullptr, 0);

    // out = relu(W_w @ feature + b_w) + x
    kfinal<<<gconv, blk, smNN>>>(w_w, feat, (float*)d_out, NC, NT, NT, NC, 0, sCT, sCT, b_w, x, sCT);
}

// round 6
// speedup vs baseline: 2.8892x; 1.9150x over previous
#include <cuda_runtime.h>
#include <cuda_bf16.h>
#include <cstdint>

// Problem constants (fixed by the reference: B=8, C=512, T=2048)
#define NB 8
#define NC 512
#define NT 2048

// ---------------- scratch (device globals; no allocation allowed) ----------
__device__ __nv_bfloat16 g_xt  [(size_t)NB * NT * NC];  // x^T     [B,T,C]
__device__ __nv_bfloat16 g_th  [(size_t)NB * NT * NC];  // theta^T [B,T,C]
__device__ __nv_bfloat16 g_ph  [(size_t)NB * NT * NC];  // phi^T   [B,T,C]
__device__ __nv_bfloat16 g_g   [(size_t)NB * NC * NT];  // g       [B,C,T]
__device__ __nv_bfloat16 g_feat[(size_t)NB * NT * NC];  // feat^T  [B,T,C]
__device__ __nv_bfloat16 g_attn[(size_t)NB * NT * NT];  // attn    [B,T,T]
__device__ float         g_sc  [(size_t)NB * NT * NT];  // scores  [B,T,T] fp32
__device__ __nv_bfloat16 g_wbf [4 * (size_t)NC * NC];   // bf16 weights

// ---------------- helpers ---------------------------------------------------
__device__ __forceinline__ uint32_t smem_u32(const void* p) {
    return (uint32_t)__cvta_generic_to_shared(p);
}
__device__ __forceinline__ void cpa16u(uint32_t dst, const void* src) {
    asm volatile("cp.async.cg.shared.global [%0], [%1], 16;" :: "r"(dst), "l"(src));
}
__device__ __forceinline__ void cpa_commit() {
    asm volatile("cp.async.commit_group;" ::: "memory");
}
template<int N>
__device__ __forceinline__ void cpa_wait() {
    asm volatile("cp.async.wait_group %0;" :: "n"(N) : "memory");
}
__device__ __forceinline__ void ldsm4(uint32_t* r, uint32_t addr) {
    asm volatile("ldmatrix.sync.aligned.m8n8.x4.shared.b16 {%0,%1,%2,%3}, [%4];"
                 : "=r"(r[0]), "=r"(r[1]), "=r"(r[2]), "=r"(r[3]) : "r"(addr));
}
__device__ __forceinline__ void mma16(float* d, const uint32_t* a, const uint32_t* b) {
    asm volatile(
        "mma.sync.aligned.m16n8k16.row.col.f32.bf16.bf16.f32 "
        "{%0,%1,%2,%3}, {%4,%5,%6,%7}, {%8,%9}, {%0,%1,%2,%3};"
        : "+f"(d[0]), "+f"(d[1]), "+f"(d[2]), "+f"(d[3])
        : "r"(a[0]), "r"(a[1]), "r"(a[2]), "r"(a[3]), "r"(b[0]), "r"(b[1]));
}
__device__ __forceinline__ __nv_bfloat16 bfr(float f) { return __float2bfloat16_rn(f); }

// ---------------- BF16 GEMM: C[M,N] = sum_k A[m,k] * B[n,k] ------------------
// A: [M,K] bf16 row-major (k contiguous), B: [N,K] bf16 row-major (k contiguous)
// EPI: 0 plain | 1 relu(acc+bias[m]) | 2 relu(acc+bias[n]) | 3 relu(acc+bias[m])+res
// OBF: store bf16 (else fp32).  CTA tile 256x128x32, 8 warps of 64x64.
template<int EPI, bool OBF>
__global__ void __launch_bounds__(256, 1)
gemm_bf(const __nv_bfloat16* __restrict__ A, const __nv_bfloat16* __restrict__ B,
        void* __restrict__ outv, int lda, int ldb, int ldo, int K,
        long long sA, long long sB, long long sO,
        const float* __restrict__ bias,
        const float* __restrict__ res, long long sR)
{
    constexpr int BM = 256, BN = 128, BK = 32, NSTG = 3;
    constexpr int LDE = 40;                 // smem row stride in elems (80 B = 5*16B)
    constexpr int A_BYT = BM * LDE * 2;     // 20480
    constexpr int B_BYT = BN * LDE * 2;     // 10240

    extern __shared__ char dsm[];
    const uint32_t smA = smem_u32(dsm);
    const uint32_t smB = smA + NSTG * A_BYT;

    const int tid = threadIdx.x;
    const int bn = blockIdx.x, bm = blockIdx.y, bz = blockIdx.z;
    const int warp = tid >> 5, lane = tid & 31;
    const int wm = warp >> 1, wn = warp & 1;
    const int r = lane & 3, q = lane >> 2;

    A += (long long)bz * sA + (long long)bm * BM * lda;
    B += (long long)bz * sB + (long long)bn * BN * ldb;
    if constexpr (EPI == 3) res += (long long)bz * sR;

    // ldmatrix per-lane row/col decomposition
    const int rowA = (lane & 7) + ((lane >> 3) & 1) * 8;   // bit3 = m-high
    const int kcA  = ((lane >> 4) & 1) * 8;                // bit4 = k-high
    const int rowB = (lane & 7) + ((lane >> 4) & 1) * 8;   // bit4 = n-high
    const int kcB  = ((lane >> 3) & 1) * 8;                // bit3 = k-high

    float acc[4][8][4];
    #pragma unroll
    for (int i = 0; i < 4; i++)
        #pragma unroll
        for (int j = 0; j < 8; j++)
            #pragma unroll
            for (int c = 0; c < 4; c++) acc[i][j][c] = 0.f;

    auto load_stage = [&](int kt, int sb) {
        const char* Ag = (const char*)A + (long long)kt * BK * 2;
        const char* Bg = (const char*)B + (long long)kt * BK * 2;
        const uint32_t as = smA + sb * A_BYT;
        const uint32_t bs = smB + sb * B_BYT;
        #pragma unroll
        for (int i = 0; i < 4; i++) {           // A: 256 rows x 64B = 1024 chunks
            const int id = tid + i * 256;
            const int row = id >> 2, c = (id & 3) * 16;
            cpa16u(as + row * 80 + c, Ag + (long long)row * lda * 2 + c);
        }
        #pragma unroll
        for (int i = 0; i < 2; i++) {           // B: 128 rows x 64B = 512 chunks
            const int id = tid + i * 256;
            const int row = id >> 2, c = (id & 3) * 16;
            cpa16u(bs + row * 80 + c, Bg + (long long)row * ldb * 2 + c);
        }
    };

    const int nk = K / BK;
    load_stage(0, 0); cpa_commit();
    load_stage(1, 1); cpa_commit();

    for (int kt = 0; kt < nk; ++kt) {
        cpa_wait<1>();
        __syncthreads();
        if (kt + 2 < nk) load_stage(kt + 2, (kt + 2) % NSTG);
        cpa_commit();

        const uint32_t aA = smA + (kt % NSTG) * A_BYT;
        const uint32_t aB = smB + (kt % NSTG) * B_BYT;

        #pragma unroll
        for (int ks = 0; ks < 2; ++ks) {
            const int kk = ks * 16;
            uint32_t af[4][4], bf[8][2];
            #pragma unroll
            for (int mt = 0; mt < 4; ++mt)
                ldsm4(af[mt], aA + ((wm * 64 + mt * 16 + rowA) * LDE + kcA + kk) * 2);
            #pragma unroll
            for (int ntp = 0; ntp < 4; ++ntp) {
                uint32_t t4[4];
                ldsm4(t4, aB + ((wn * 64 + ntp * 16 + rowB) * LDE + kcB + kk) * 2);
                bf[2 * ntp + 0][0] = t4[0]; bf[2 * ntp + 0][1] = t4[1];
                bf[2 * ntp + 1][0] = t4[2]; bf[2 * ntp + 1][1] = t4[3];
            }
            #pragma unroll
            for (int mt = 0; mt < 4; ++mt)
                #pragma unroll
                for (int nt = 0; nt < 8; ++nt)
                    mma16(acc[mt][nt], af[mt], bf[nt]);
        }
    }

    // ---- epilogue: c0,c1 -> (row q, cols 2r,2r+1); c2,c3 -> row q+8 ---------
    #pragma unroll
    for (int mt = 0; mt < 4; ++mt) {
        #pragma unroll
        for (int h = 0; h < 2; ++h) {
            const int row = bm * BM + wm * 64 + mt * 16 + h * 8 + q;
            float bv = 0.f;
            if constexpr (EPI == 1 || EPI == 3) bv = bias[row];
            const long long obase = (long long)bz * sO + (long long)row * ldo;
            #pragma unroll
            for (int nt = 0; nt < 8; ++nt) {
                const int gn = bn * BN + wn * 64 + nt * 8 + 2 * r;
                float c0 = acc[mt][nt][2 * h + 0];
                float c1 = acc[mt][nt][2 * h + 1];
                if constexpr (EPI == 1 || EPI == 3) {
                    c0 = fmaxf(c0 + bv, 0.f);
                    c1 = fmaxf(c1 + bv, 0.f);
                } else if constexpr (EPI == 2) {
                    c0 = fmaxf(c0 + bias[gn], 0.f);
                    c1 = fmaxf(c1 + bias[gn + 1], 0.f);
                }
                if constexpr (EPI == 3) {
                    const float* rp = res + (long long)row * ldo + gn;
                    c0 += rp[0]; c1 += rp[1];
                }
                if constexpr (OBF) {
                    __nv_bfloat162 v; v.x = bfr(c0); v.y = bfr(c1);
                    *(__nv_bfloat162*)((__nv_bfloat16*)outv + obase + gn) = v;
                } else {
                    float2 v; v.x = c0; v.y = c1;
                    *(float2*)((float*)outv + obase + gn) = v;
                }
            }
        }
    }
}

// ---------------- x transpose: [B,C,T] fp32 -> [B,T,C] bf16 ------------------
__global__ void __launch_bounds__(256, 4)
transpose_x(const float* __restrict__ x, __nv_bfloat16* __restrict__ xt)
{
    __shared__ float s[32][33];
    const int bz = blockIdx.z;
    const float* xp = x + (size_t)bz * NC * NT;
    __nv_bfloat16* op = xt + (size_t)bz * NT * NC;
    const int c0 = blockIdx.y * 32, t0 = blockIdx.x * 32;
    const int tid = threadIdx.x;
    {
        const int c = tid >> 3, tq = (tid & 7) * 4;
        float4 v = *(const float4*)&xp[(size_t)(c0 + c) * NT + t0 + tq];
        s[c][tq + 0] = v.x; s[c][tq + 1] = v.y;
        s[c][tq + 2] = v.z; s[c][tq + 3] = v.w;
    }
    __syncthreads();
    {
        const int t = tid >> 3, cb = (tid & 7) * 4;
        __nv_bfloat162 u0, u1;
        u0.x = bfr(s[cb + 0][t]); u0.y = bfr(s[cb + 1][t]);
        u1.x = bfr(s[cb + 2][t]); u1.y = bfr(s[cb + 3][t]);
        __nv_bfloat16* o = &op[(size_t)(t0 + t) * NC + c0 + cb];
        *(__nv_bfloat162*)(o + 0) = u0;
        *(__nv_bfloat162*)(o + 2) = u1;
    }
}

// ---------------- fp32 -> bf16 copy (weights) --------------------------------
__global__ void __launch_bounds__(256, 8)
f2bf(const float* __restrict__ in, __nv_bfloat16* __restrict__ o, int n)
{
    const int i = (blockIdx.x * 256 + threadIdx.x) * 4;
    if (i < n) {
        float4 v = *(const float4*)(in + i);
        __nv_bfloat162 a, b;
        a.x = bfr(v.x); a.y = bfr(v.y);
        b.x = bfr(v.z); b.y = bfr(v.w);
        *(__nv_bfloat162*)(o + i)     = a;
        *(__nv_bfloat162*)(o + i + 2) = b;
    }
}

// ---------------- softmax: fp32 scores row -> bf16 attn row ------------------
__global__ void __launch_bounds__(256, 4)
softmax2048(const float* __restrict__ S, __nv_bfloat16* __restrict__ P)
{
    const size_t roff = ((size_t)blockIdx.y * NT + blockIdx.x) * NT;
    const float* row = S + roff;
    __nv_bfloat16* prow = P + roff;
    const int tid = threadIdx.x;
    const int warp = tid >> 5, lane = tid & 31;

    float4 v0 = ((const float4*)row)[tid];
    float4 v1 = ((const float4*)row)[tid + 256];

    float mx = fmaxf(fmaxf(fmaxf(v0.x, v0.y), fmaxf(v0.z, v0.w)),
                     fmaxf(fmaxf(v1.x, v1.y), fmaxf(v1.z, v1.w)));
    #pragma unroll
    for (int o = 16; o; o >>= 1) mx = fmaxf(mx, __shfl_xor_sync(0xffffffffu, mx, o));

    __shared__ float sm[8], ss[8];
    if (!lane) sm[warp] = mx;
    __syncthreads();
    mx = sm[0];
    #pragma unroll
    for (int i = 1; i < 8; i++) mx = fmaxf(mx, sm[i]);

    v0.x = __expf(v0.x - mx); v0.y = __expf(v0.y - mx);
    v0.z = __expf(v0.z - mx); v0.w = __expf(v0.w - mx);
    v1.x = __expf(v1.x - mx); v1.y = __expf(v1.y - mx);
    v1.z = __expf(v1.z - mx); v1.w = __expf(v1.w - mx);

    float s = v0.x + v0.y + v0.z + v0.w + v1.x + v1.y + v1.z + v1.w;
    #pragma unroll
    for (int o = 16; o; o >>= 1) s += __shfl_xor_sync(0xffffffffu, s, o);
    if (!lane) ss[warp] = s;
    __syncthreads();
    s = ss[0];
    #pragma unroll
    for (int i = 1; i < 8; i++) s += ss[i];

    const float inv = 1.0f / s;
    __nv_bfloat162 a0, a1, b0, b1;
    a0.x = bfr(v0.x * inv); a0.y = bfr(v0.y * inv);
    a1.x = bfr(v0.z * inv); a1.y = bfr(v0.w * inv);
    b0.x = bfr(v1.x * inv); b0.y = bfr(v1.y * inv);
    b1.x = bfr(v1.z * inv); b1.y = bfr(v1.w * inv);
    ((__nv_bfloat162*)prow)[2 * tid + 0]   = a0;
    ((__nv_bfloat162*)prow)[2 * tid + 1]   = a1;
    ((__nv_bfloat162*)prow)[2 * (tid + 256) + 0] = b0;
    ((__nv_bfloat162*)prow)[2 * (tid + 256) + 1] = b1;
}

// ---------------- launch ----------------------------------------------------
extern "C" void kernel_launch(void* const* d_in, const int* in_sizes, int n_in,
                              void* d_out, int out_size)
{
    const float* x       = (const float*)d_in[0];
    const float* w_theta = (const float*)d_in[1];
    const float* b_theta = (const float*)d_in[2];
    const float* w_phi   = (const float*)d_in[3];
    const float* b_phi   = (const float*)d_in[4];
    const float* w_g     = (const float*)d_in[5];
    const float* b_g     = (const float*)d_in[6];
    const float* w_w     = (const float*)d_in[7];
    const float* b_w     = (const float*)d_in[8];

    void *pxt, *pth, *pph, *pg, *pf, *pa, *ps, *pw;
    cudaGetSymbolAddress(&pxt, g_xt);
    cudaGetSymbolAddress(&pth, g_th);
    cudaGetSymbolAddress(&pph, g_ph);
    cudaGetSymbolAddress(&pg,  g_g);
    cudaGetSymbolAddress(&pf,  g_feat);
    cudaGetSymbolAddress(&pa,  g_attn);
    cudaGetSymbolAddress(&ps,  g_sc);
    cudaGetSymbolAddress(&pw,  g_wbf);
    __nv_bfloat16* xt   = (__nv_bfloat16*)pxt;
    __nv_bfloat16* th   = (__nv_bfloat16*)pth;
    __nv_bfloat16* ph   = (__nv_bfloat16*)pph;
    __nv_bfloat16* gg   = (__nv_bfloat16*)pg;
    __nv_bfloat16* ft   = (__nv_bfloat16*)pf;
    __nv_bfloat16* attn = (__nv_bfloat16*)pa;
    float*         sc   = (float*)ps;
    __nv_bfloat16* wbf  = (__nv_bfloat16*)pw;
    __nv_bfloat16* wT = wbf;
    __nv_bfloat16* wP = wbf + (size_t)NC * NC;
    __nv_bfloat16* wG = wbf + 2 * (size_t)NC * NC;
    __nv_bfloat16* wW = wbf + 3 * (size_t)NC * NC;

    const long long sCT = (long long)NC * NT;
    const long long sTT = (long long)NT * NT;

    auto kconvT = gemm_bf<2, true >;   // theta^T/phi^T: A=xt, B=W, col bias
    auto kconvG = gemm_bf<1, true >;   // g: A=W, B=xt, row bias
    auto kscore = gemm_bf<0, false>;   // scores fp32
    auto kfeat  = gemm_bf<0, true >;   // feat^T = attn @ g^T
    auto kfinal = gemm_bf<3, false>;   // relu(W.f+b)+x, fp32 out

    const int SMEM = 3 * (20480 + 10240);   // 92160
    cudaFuncSetAttribute(kconvT, cudaFuncAttributeMaxDynamicSharedMemorySize, SMEM);
    cudaFuncSetAttribute(kconvG, cudaFuncAttributeMaxDynamicSharedMemorySize, SMEM);
    cudaFuncSetAttribute(kscore, cudaFuncAttributeMaxDynamicSharedMemorySize, SMEM);
    cudaFuncSetAttribute(kfeat,  cudaFuncAttributeMaxDynamicSharedMemorySize, SMEM);
    cudaFuncSetAttribute(kfinal, cudaFuncAttributeMaxDynamicSharedMemorySize, SMEM);

    dim3 blk(256);
    const int NW = NC * NC;

    // 0) weights -> bf16 ; x -> x^T bf16
    f2bf<<<NW / 1024, blk>>>(w_theta, wT, NW);
    f2bf<<<NW / 1024, blk>>>(w_phi,   wP, NW);
    f2bf<<<NW / 1024, blk>>>(w_g,     wG, NW);
    f2bf<<<NW / 1024, blk>>>(w_w,     wW, NW);
    transpose_x<<<dim3(NT / 32, NC / 32, NB), blk>>>(x, xt);

    // 1) theta^T[t,o] = relu(sum_c xt[t,c] W[o,c] + b[o])   (M=T, N=C)
    kconvT<<<dim3(NC / 128, NT / 256, NB), blk, SMEM>>>(
        xt, wT, th, NC, NC, NC, NC, sCT, 0, sCT, b_theta, nullptr, 0);
    kconvT<<<dim3(NC / 128, NT / 256, NB), blk, SMEM>>>(
        xt, wP, ph, NC, NC, NC, NC, sCT, 0, sCT, b_phi, nullptr, 0);

    // 2) g[o,t] = relu(sum_c W[o,c] xt[t,c] + b[o])          (M=C, N=T)
    kconvG<<<dim3(NT / 128, NC / 256, NB), blk, SMEM>>>(
        wG, xt, gg, NC, NC, NT, NC, 0, sCT, sCT, b_g, nullptr, 0);

    // 3) scores[i,j] = sum_c theta^T[i,c] phi^T[j,c]         (M=T, N=T) fp32
    kscore<<<dim3(NT / 128, NT / 256, NB), blk, SMEM>>>(
        th, ph, sc, NC, NC, NT, NC, sCT, sCT, sTT, nullptr, nullptr, 0);

    // 4) softmax over j -> bf16 attn
    softmax2048<<<dim3(NT, NB), blk>>>(sc, attn);

    // 5) feat^T[i,c] = sum_j attn[i,j] g[c,j]                (M=T, N=C, K=T)
    kfeat<<<dim3(NC / 128, NT / 256, NB), blk, SMEM>>>(
        attn, gg, ft, NT, NT, NC, NT, sTT, sCT, sCT, nullptr, nullptr, 0);

    // 6) out[o,t] = relu(sum_c Ww[o,c] feat^T[t,c] + b[o]) + x[o,t]  (M=C, N=T)
    kfinal<<<dim3(NT / 128, NC / 256, NB), blk, SMEM>>>(
        wW, ft, d_out, NC, NC, NT, NC, 0, sCT, sCT, b_w, x, sCT);
}